// round 6
// baseline (speedup 1.0000x reference)
#include <cuda_runtime.h>
#include <cstdint>

// SpikeFP32Multiplier, warp-cooperative ballot version, v4.
// Lane l owns memory word (31-l): ballot bit l == IEEE bit l (no brev).
// v4: ELEMS_PER_WARP=16 with phase-separated bursts — 32 LDGs back-to-back,
// then all ballots/multiplies, then 16 STGs back-to-back — to minimize
// DRAM read/write turnarounds (DRAM cycles-active plateaued at 85%).

static constexpr int ELEMS_PER_WARP = 16;

__global__ void __launch_bounds__(256)
spike_fp32_mul_ballot4(const uint32_t* __restrict__ A,
                       const uint32_t* __restrict__ B,
                       uint32_t* __restrict__ out,
                       int n_elems) {
    const int lane = threadIdx.x & 31;
    const int warp = (blockIdx.x * blockDim.x + threadIdx.x) >> 5;
    const int e0 = warp * ELEMS_PER_WARP;
    if (e0 >= n_elems) return;

    const int w = 31 - lane;  // memory word owned by this lane

    // Phase 1: read burst — 32 outstanding LDG.32 per lane.
    uint32_t a[ELEMS_PER_WARP], b[ELEMS_PER_WARP];
#pragma unroll
    for (int i = 0; i < ELEMS_PER_WARP; ++i) {
        size_t off = (size_t)(e0 + i) * 32 + w;
        a[i] = __ldcs(A + off);
        b[i] = __ldcs(B + off);
    }

    // Phase 2: pack / multiply / select (no memory traffic).
    uint32_t v[ELEMS_PER_WARP];
#pragma unroll
    for (int i = 0; i < ELEMS_PER_WARP; ++i) {
        uint32_t ua = __ballot_sync(0xFFFFFFFFu, a[i] != 0u);
        uint32_t ub = __ballot_sync(0xFFFFFFFFu, b[i] != 0u);
        // IEEE-754 fp32 multiply, RNE, subnormal-aware (no -ftz).
        uint32_t up = __float_as_uint(__uint_as_float(ua) * __uint_as_float(ub));
        v[i] = ((up >> lane) & 1u) ? 0x3F800000u : 0u;
    }

    // Phase 3: write burst — 16 STG.32 back-to-back.
#pragma unroll
    for (int i = 0; i < ELEMS_PER_WARP; ++i) {
        __stcs(out + (size_t)(e0 + i) * 32 + w, v[i]);
    }
}

extern "C" void kernel_launch(void* const* d_in, const int* in_sizes, int n_in,
                              void* d_out, int out_size) {
    const uint32_t* A = (const uint32_t*)d_in[0];
    const uint32_t* B = (const uint32_t*)d_in[1];
    uint32_t* out = (uint32_t*)d_out;

    int n_elems = in_sizes[0] / 32;

    const int block = 256;  // 8 warps per block
    int warps_needed = (n_elems + ELEMS_PER_WARP - 1) / ELEMS_PER_WARP;
    int grid = (warps_needed * 32 + block - 1) / block;
    spike_fp32_mul_ballot4<<<grid, block>>>(A, B, out, n_elems);
}

// round 7
// speedup vs baseline: 1.0148x; 1.0148x over previous
#include <cuda_runtime.h>
#include <cstdint>

// SpikeFP32Multiplier, warp-cooperative ballot version, v5 (consolidation).
// Lane l owns memory word (31-l): ballot bit l == IEEE bit l (no brev).
// Confirmed HBM-bound at ~6.8 TB/s on fixed 768 MB traffic (roofline).
// v5 = v3's best config (ELEMS=8, regs~26) + phase-separated bursts,
// block=512 to halve CTA dispatch overhead.

static constexpr int ELEMS_PER_WARP = 8;

__global__ void __launch_bounds__(512)
spike_fp32_mul_ballot5(const uint32_t* __restrict__ A,
                       const uint32_t* __restrict__ B,
                       uint32_t* __restrict__ out,
                       int n_elems) {
    const int lane = threadIdx.x & 31;
    const int warp = (blockIdx.x * blockDim.x + threadIdx.x) >> 5;
    const int e0 = warp * ELEMS_PER_WARP;
    if (e0 >= n_elems) return;

    const int w = 31 - lane;  // memory word owned by this lane

    // Phase 1: read burst — 16 outstanding LDG.32 per lane (MLP=16).
    uint32_t a[ELEMS_PER_WARP], b[ELEMS_PER_WARP];
#pragma unroll
    for (int i = 0; i < ELEMS_PER_WARP; ++i) {
        size_t off = (size_t)(e0 + i) * 32 + w;
        a[i] = __ldcs(A + off);
        b[i] = __ldcs(B + off);
    }

    // Phase 2: pack / IEEE fp32 multiply (RNE, subnormal-aware) / select.
    uint32_t v[ELEMS_PER_WARP];
#pragma unroll
    for (int i = 0; i < ELEMS_PER_WARP; ++i) {
        uint32_t ua = __ballot_sync(0xFFFFFFFFu, a[i] != 0u);
        uint32_t ub = __ballot_sync(0xFFFFFFFFu, b[i] != 0u);
        uint32_t up = __float_as_uint(__uint_as_float(ua) * __uint_as_float(ub));
        v[i] = ((up >> lane) & 1u) ? 0x3F800000u : 0u;
    }

    // Phase 3: write burst — 8 STG.32 back-to-back.
#pragma unroll
    for (int i = 0; i < ELEMS_PER_WARP; ++i) {
        __stcs(out + (size_t)(e0 + i) * 32 + w, v[i]);
    }
}

extern "C" void kernel_launch(void* const* d_in, const int* in_sizes, int n_in,
                              void* d_out, int out_size) {
    const uint32_t* A = (const uint32_t*)d_in[0];
    const uint32_t* B = (const uint32_t*)d_in[1];
    uint32_t* out = (uint32_t*)d_out;

    int n_elems = in_sizes[0] / 32;

    const int block = 512;  // 16 warps per block
    int warps_needed = (n_elems + ELEMS_PER_WARP - 1) / ELEMS_PER_WARP;
    int grid = (warps_needed * 32 + block - 1) / block;
    spike_fp32_mul_ballot5<<<grid, block>>>(A, B, out, n_elems);
}